// round 16
// baseline (speedup 1.0000x reference)
#include <cuda_runtime.h>
#include <cstdint>

// Appro_WAConv2d: depthwise 7x7 conv with mantissa-approximation factor.
//   term = x*w*(f1+f2-1)/(f1*f2) = u*w + s*(w/f2),  u = x/f1, s = x - u
// Packed f32x2: smem {u,s} float2, weights {w, w/f2}; one fma.rn.f32x2/tap.
// Round-16: 4-row x 2-float tile made register-feasible via cp.async.
//   Stage A: register-free LDGSTS of raw x into smem scratch (lands
//   during stage B). Stage C: wait_group 0, then raw->pair conversion
//   (same-thread cells: no extra barrier). Stage B live set = p[8] pairs
//   + acc[4][2] ~= 50 regs <= 58 cap (224 thr, occ-5).
//   Input crossbar wavefronts per output float: 1.0 -> 0.625.

#define B_   4
#define C_   192
#define H_   56
#define W_   56
#define K_   7
#define PAD_ 3
#define HR    28            // output rows per tile (half plane)
#define SMROWS 34           // 28 + 2*3 halo rows
#define SMC   62            // pairs per row (= float cols incl. halo)
#define NTHR  224           // 7 full warps; 196 compute in stage B
#define CELLS (SMROWS * SMC)  // 2108
#define LITER 10            // ceil(CELLS / NTHR)
#define NTILES (B_ * C_ * 2)  // 1536
#define NBLK  760           // 152 SMs * 5 resident blocks
#define SWPAD (K_ * 8)      // 56 weight pairs (7 rows padded to 8)

__device__ unsigned int g_tile_ctr;
__global__ void reset_ctr_kernel() { g_tile_ctr = 0u; }

// division-free split: u ~= v/f1 (signed power of 2), s = v - u.
__device__ __forceinline__ float2 usplit(float v) {
    float a = fabsf(v) + 1e-7f;
    unsigned ab = __float_as_uint(a);
    unsigned ub = (__float_as_uint(v) & 0x80000000u)
                | ((ab & 0x7F800000u) + ((ab & 0x00400000u) << 1));
    float u = __uint_as_float(ub);
    return make_float2(u, v - u);
}

__device__ __forceinline__ unsigned long long fma2(unsigned long long a,
                                                   unsigned long long b,
                                                   unsigned long long c) {
    unsigned long long d;
    asm("fma.rn.f32x2 %0, %1, %2, %3;" : "=l"(d) : "l"(a), "l"(b), "l"(c));
    return d;
}

__device__ __forceinline__ float pairsum(unsigned long long v) {
    return __uint_as_float((unsigned)v) + __uint_as_float((unsigned)(v >> 32));
}

__device__ __forceinline__ void cp_async4(uint32_t dst, const float* src) {
    asm volatile("cp.async.ca.shared.global [%0], [%1], 4;"
                 :: "r"(dst), "l"(src));
}
__device__ __forceinline__ void sts_zero(uint32_t dst) {
    asm volatile("st.shared.u32 [%0], 0;" :: "r"(dst));
}

// dynamic smem: pairs[2][CELLS] float2 | raw[CELLS] float | sw[2][SWPAD] float2
extern __shared__ __align__(16) char dynraw[];

__global__ __launch_bounds__(NTHR, 5)
void waconv_kernel(const float* __restrict__ x,
                   const float* __restrict__ w,
                   float* __restrict__ out) {
    float2* const sm0 = (float2*)dynraw;
    float2* const sm1 = sm0 + CELLS;
    float*  const raw = (float*)(sm1 + CELLS);
    float2* const sw0 = (float2*)(raw + CELLS);
    float2* const sw1 = sw0 + SWPAD;
    __shared__ int sh_cur;
    __shared__ int sh_next[2];

    const int tid = threadIdx.x;
    const uint32_t raw_s = (uint32_t)__cvta_generic_to_shared(raw);

    // base (r,q) for this thread's cells; advanced incrementally per kk
    const int r00 = tid / SMC;
    const int q00 = tid - r00 * SMC;

    // ---- grab first two tiles ----
    if (tid == 0) {
        sh_cur     = (int)atomicAdd(&g_tile_ctr, 1u);
        sh_next[0] = (int)atomicAdd(&g_tile_ctr, 1u);
    }
    __syncthreads();
    int cur = sh_cur;
    if (cur >= NTILES) return;

    // ---- prologue: direct fill of buffer 0 with tile cur ----
    {
        const int plane = cur >> 1;
        const int h0 = (cur & 1) * HR;
        const float* __restrict__ xp = x + (size_t)plane * (H_ * W_);
        if (tid < SWPAD) {
            int j = tid & 7;
            float2 v2 = make_float2(0.0f, 0.0f);
            if (j < K_) {
                float wv = w[(plane % C_) * (K_ * K_) + (tid >> 3) * K_ + j];
                v2 = make_float2(wv, usplit(wv).x);
            }
            sw0[tid] = v2;
        }
        int r = r00, q = q00;
#pragma unroll
        for (int kk = 0; kk < LITER; ++kk) {
            int idx = tid + kk * NTHR;
            if (idx < CELLS) {
                int iy = h0 + r - PAD_, ix = q - PAD_;
                float v = 0.0f;
                if ((unsigned)iy < H_ && (unsigned)ix < W_) v = xp[iy * W_ + ix];
                sm0[idx] = usplit(v);
            }
            r += 3; q += 38; if (q >= SMC) { q -= SMC; r += 1; }  // +224
        }
    }
    __syncthreads();

    // compute-thread coordinates (4 rows x 2 floats; 196 active)
    const int ty = tid / 28;               // 0..7 (>=7 inactive)
    const int tx = tid - ty * 28;          // 0..27
    const int y0 = ty * 4;                 // local output rows y0..y0+3
    const int c0 = tx * 2;                 // output float col (pair col c0)
    const bool active = (tid < 196);

    // ---- persistent tile loop (one tile lookahead) ----
    int it = 0;
    while (cur < NTILES) {
        const int nxt = sh_next[it & 1];
        const int buf = it & 1;
        const bool more = (nxt < NTILES);
        const int plane = cur >> 1;
        const int h0 = (cur & 1) * HR;

        // stage A: register-free cp.async of next tile's raw x into smem
        int nplane = 0;
        if (more) {
            nplane = nxt >> 1;
            const int nh0 = (nxt & 1) * HR;
            const float* __restrict__ xp = x + (size_t)nplane * (H_ * W_);
            int r = r00, q = q00;
#pragma unroll
            for (int kk = 0; kk < LITER; ++kk) {
                int idx = tid + kk * NTHR;
                if (idx < CELLS) {
                    int iy = nh0 + r - PAD_, ix = q - PAD_;
                    uint32_t dst = raw_s + (uint32_t)idx * 4u;
                    if ((unsigned)iy < H_ && (unsigned)ix < W_)
                        cp_async4(dst, xp + iy * W_ + ix);
                    else
                        sts_zero(dst);
                }
                r += 3; q += 38; if (q >= SMC) { q -= SMC; r += 1; }
            }
            asm volatile("cp.async.commit_group;" ::: "memory");
        }

        // stage B: compute 4x2 tile from sm[buf]
        if (active) {
            const float2* __restrict__ smb = buf ? sm1 : sm0;
            const ulonglong2* __restrict__ swq =
                (const ulonglong2*)(buf ? sw1 : sw0);
            unsigned long long acc[4][2];
#pragma unroll
            for (int a = 0; a < 4; ++a) { acc[a][0] = 0ull; acc[a][1] = 0ull; }

#pragma unroll
            for (int t = 0; t < 10; ++t) {       // input row = y0 + t
                const unsigned long long* pr =
                    (const unsigned long long*)&smb[(y0 + t) * SMC + c0];
                unsigned long long p[8];
                ((ulonglong2*)p)[0] = ((const ulonglong2*)pr)[0];
                ((ulonglong2*)p)[1] = ((const ulonglong2*)pr)[1];
                ((ulonglong2*)p)[2] = ((const ulonglong2*)pr)[2];
                ((ulonglong2*)p)[3] = ((const ulonglong2*)pr)[3];
#pragma unroll
                for (int oy = 0; oy < 4; ++oy) {
                    const int i = t - oy;        // kernel row, compile-time
                    if (i < 0 || i > 6) continue;
#pragma unroll
                    for (int jj = 0; jj < 4; ++jj) {
                        ulonglong2 wp = swq[(i << 2) + jj];  // LDS.128 bcast
                        const int j0 = 2 * jj;
                        acc[oy][0] = fma2(p[j0],     wp.x, acc[oy][0]);
                        acc[oy][1] = fma2(p[j0 + 1], wp.x, acc[oy][1]);
                        if (j0 + 1 < K_) {
                            acc[oy][0] = fma2(p[j0 + 1], wp.y, acc[oy][0]);
                            acc[oy][1] = fma2(p[j0 + 2], wp.y, acc[oy][1]);
                        }
                    }
                }
            }
            float* op = out + (size_t)plane * (H_ * W_) + (h0 + y0) * W_ + c0;
#pragma unroll
            for (int oy = 0; oy < 4; ++oy)
                *(float2*)(op + oy * W_) =
                    make_float2(pairsum(acc[oy][0]), pairsum(acc[oy][1]));
        }

        // grab tile after next (visible after the barrier below)
        if (tid == 0)
            sh_next[(it + 1) & 1] = (int)atomicAdd(&g_tile_ctr, 1u);

        // stage C: convert raw -> {u,s} pairs into the other buffer
        if (more) {
            asm volatile("cp.async.wait_group 0;" ::: "memory");
            float2* const smn = buf ? sm0 : sm1;
            if (tid < SWPAD) {
                int j = tid & 7;
                float2 v2 = make_float2(0.0f, 0.0f);
                if (j < K_) {
                    float wv = w[(nplane % C_) * (K_ * K_) + (tid >> 3) * K_ + j];
                    v2 = make_float2(wv, usplit(wv).x);
                }
                (buf ? sw0 : sw1)[tid] = v2;
            }
#pragma unroll
            for (int kk = 0; kk < LITER; ++kk) {
                int idx = tid + kk * NTHR;
                if (idx < CELLS) smn[idx] = usplit(raw[idx]);
            }
        }
        __syncthreads();
        cur = nxt;
        ++it;
    }
}

#define SMEM_BYTES ((2 * CELLS + 2 * SWPAD) * (int)sizeof(float2) \
                    + CELLS * (int)sizeof(float))

extern "C" void kernel_launch(void* const* d_in, const int* in_sizes, int n_in,
                              void* d_out, int out_size) {
    const float* x  = (const float*)d_in[0];   // (4,192,56,56) f32
    const float* wt = (const float*)d_in[1];   // (192,1,7,7)  f32
    float* out = (float*)d_out;                // (4,192,56,56) f32
    (void)in_sizes; (void)n_in; (void)out_size;
    static int configured = 0;
    if (!configured) {
        cudaFuncSetAttribute(waconv_kernel,
                             cudaFuncAttributeMaxDynamicSharedMemorySize,
                             SMEM_BYTES);
        configured = 1;
    }
    reset_ctr_kernel<<<1, 1>>>();
    waconv_kernel<<<NBLK, NTHR, SMEM_BYTES>>>(x, wt, out);
}

// round 17
// speedup vs baseline: 1.8901x; 1.8901x over previous
#include <cuda_runtime.h>

// Appro_WAConv2d: depthwise 7x7 conv with mantissa-approximation factor.
//   term = x*w*(f1+f2-1)/(f1*f2) = u*w + s*(w/f2),  u = x/f1, s = x - u
// Packed f32x2: smem {u,s} float2, weights {w, w/f2}; one fma.rn.f32x2/tap.
// Round-17: consolidation on the proven R13 shape (half-plane persistent
// tiles, double-buffered A/B/C pipeline, occ-3, usplit, weight-row
// register rotation). Single change: paired-cell mapping in the fill
// paths — each thread owns 2 adjacent cells (same smem row, idx even),
// halving index/predicate instructions and turning 6 STS.64 into
// 3 STS.128 per thread-tile. Stage B untouched.
// Falsified levers (do not retry): bigger tiles (reg-infeasible R11/R14),
// reg caps <48 (remat R5/R8/R12), work stealing (R15), 4B cp.async (R16).

#define B_   4
#define C_   192
#define H_   56
#define W_   56
#define K_   7
#define PAD_ 3
#define HR    28            // output rows per tile (half plane)
#define SMROWS 34           // 28 + 2*3 halo rows
#define SR    64            // smem row stride in float2 (pow2 indexing)
#define NTHR  392
#define CELLS (SMROWS * SR) // 2176
#define HCELLS (CELLS / 2)  // 1088 cell-pairs
#define NTILES (B_ * C_ * 2)  // 1536
#define NBLK  456           // 152 SMs * 3 resident blocks

// division-free split: u ~= v/f1 (signed power of 2), s = v - u.
// f1 = mantissa-map(|v|+eps) shares the mantissa of a=|v|+eps, so a/f1 is
// exactly 2^(exp(a) + topbit); dropped eps-scale term is O(1e-7).
__device__ __forceinline__ float2 usplit(float v) {
    float a = fabsf(v) + 1e-7f;
    unsigned ab = __float_as_uint(a);
    unsigned ub = (__float_as_uint(v) & 0x80000000u)
                | ((ab & 0x7F800000u) + ((ab & 0x00400000u) << 1));
    float u = __uint_as_float(ub);
    return make_float2(u, v - u);
}

__device__ __forceinline__ unsigned long long fma2(unsigned long long a,
                                                   unsigned long long b,
                                                   unsigned long long c) {
    unsigned long long d;
    asm("fma.rn.f32x2 %0, %1, %2, %3;" : "=l"(d) : "l"(a), "l"(b), "l"(c));
    return d;
}

__device__ __forceinline__ float pairsum(unsigned long long v) {
    return __uint_as_float((unsigned)v) + __uint_as_float((unsigned)(v >> 32));
}

__global__ __launch_bounds__(NTHR, 3)
void waconv_kernel(const float* __restrict__ x,
                   const float* __restrict__ w,
                   float* __restrict__ out) {
    __shared__ __align__(16) float2 sm[2][CELLS];     // {u, s} interleaved
    __shared__ __align__(16) float2 sw[2][K_ * 8];    // {w, w/f2}, rows of 8

    const int tid = threadIdx.x;
    const int t0 = (int)(((long long)blockIdx.x       * NTILES) / NBLK);
    const int t1 = (int)(((long long)(blockIdx.x + 1) * NTILES) / NBLK);

    const int ty = tid / 28;               // 0..13
    const int tx = tid - ty * 28;          // 0..27
    const int y0 = ty * 2;
    const int x0 = tx * 2;

    // ---- prologue: fill buffer 0 with tile t0 (paired cells) ----
    {
        const int plane = t0 >> 1;
        const int h0 = (t0 & 1) * HR;
        const float* __restrict__ xp = x + (size_t)plane * (H_ * W_);
        if (tid < K_ * 8) {
            int j = tid & 7;
            float2 v2 = make_float2(0.0f, 0.0f);
            if (j < K_) {
                float wv = w[(plane % C_) * (K_ * K_) + (tid >> 3) * K_ + j];
                v2 = make_float2(wv, usplit(wv).x);   // {w, ~w/f2}
            }
            sw[0][tid] = v2;
        }
#pragma unroll
        for (int kk = 0; kk < 3; ++kk) {
            int pid = tid + kk * NTHR;
            if (pid < HCELLS) {
                int idx = pid * 2;
                int r = idx >> 6, q = idx & 63;      // q even
                if (q < 62) {                         // skip padding cols
                    int iy = h0 + r - PAD_;
                    float v0 = 0.0f, v1 = 0.0f;
                    if ((unsigned)iy < H_) {
                        int ix0 = q - PAD_;
                        if ((unsigned)ix0 < W_)       v0 = xp[iy * W_ + ix0];
                        if ((unsigned)(ix0 + 1) < W_) v1 = xp[iy * W_ + ix0 + 1];
                    }
                    float2 a = usplit(v0), b = usplit(v1);
                    *(float4*)&sm[0][idx] = make_float4(a.x, a.y, b.x, b.y);
                }
            }
        }
    }
    __syncthreads();

    // ---- persistent tile loop ----
    for (int k = t0; k < t1; ++k) {
        const int buf = (k - t0) & 1;
        const int plane = k >> 1;
        const int h0 = (k & 1) * HR;
        const bool more = (k + 1 < t1);

        // stage A: issue next tile's global loads (6 independent LDGs)
        float va[3], vb[3];
        int nplane = 0;
        if (more) {
            const int nt = k + 1;
            nplane = nt >> 1;
            const int nh0 = (nt & 1) * HR;
            const float* __restrict__ xp = x + (size_t)nplane * (H_ * W_);
#pragma unroll
            for (int kk = 0; kk < 3; ++kk) {
                int pid = tid + kk * NTHR;
                float v0 = 0.0f, v1 = 0.0f;
                if (pid < HCELLS) {
                    int idx = pid * 2;
                    int r = idx >> 6, q = idx & 63;
                    int iy = nh0 + r - PAD_;
                    if (q < 62 && (unsigned)iy < H_) {
                        int ix0 = q - PAD_;
                        if ((unsigned)ix0 < W_)       v0 = __ldg(xp + iy * W_ + ix0);
                        if ((unsigned)(ix0 + 1) < W_) v1 = __ldg(xp + iy * W_ + ix0 + 1);
                    }
                }
                va[kk] = v0; vb[kk] = v1;
            }
        }

        // stage B: compute current tile from sm[buf] (unchanged from R13)
        {
            const ulonglong2* __restrict__ swq = (const ulonglong2*)sw[buf];
            const float2* __restrict__ smb = sm[buf];
            unsigned long long acc00 = 0ull, acc01 = 0ull,
                               acc10 = 0ull, acc11 = 0ull;
            ulonglong2 wcur[4], wprev[4];
#pragma unroll
            for (int t = 0; t < 8; ++t) {
                const unsigned long long* pr =
                    (const unsigned long long*)&smb[((y0 + t) << 6) + x0];
                unsigned long long p[8];
                ((ulonglong2*)p)[0] = ((const ulonglong2*)pr)[0];
                ((ulonglong2*)p)[1] = ((const ulonglong2*)pr)[1];
                ((ulonglong2*)p)[2] = ((const ulonglong2*)pr)[2];
                ((ulonglong2*)p)[3] = ((const ulonglong2*)pr)[3];

                if (t <= 6) {
#pragma unroll
                    for (int jj = 0; jj < 4; ++jj)
                        wcur[jj] = swq[(t << 2) + jj];     // LDS.128 bcast
                }
                // oy = 0 uses kernel row i = t (valid t<=6)
                if (t <= 6) {
#pragma unroll
                    for (int jj = 0; jj < 4; ++jj) {
                        const int j0 = 2 * jj;
                        acc00 = fma2(p[j0],     wcur[jj].x, acc00);
                        acc01 = fma2(p[j0 + 1], wcur[jj].x, acc01);
                        if (j0 + 1 < K_) {
                            acc00 = fma2(p[j0 + 1], wcur[jj].y, acc00);
                            acc01 = fma2(p[j0 + 2], wcur[jj].y, acc01);
                        }
                    }
                }
                // oy = 1 uses kernel row i = t-1 (valid t>=1)
                if (t >= 1) {
#pragma unroll
                    for (int jj = 0; jj < 4; ++jj) {
                        const int j0 = 2 * jj;
                        acc10 = fma2(p[j0],     wprev[jj].x, acc10);
                        acc11 = fma2(p[j0 + 1], wprev[jj].x, acc11);
                        if (j0 + 1 < K_) {
                            acc10 = fma2(p[j0 + 1], wprev[jj].y, acc10);
                            acc11 = fma2(p[j0 + 2], wprev[jj].y, acc11);
                        }
                    }
                }
#pragma unroll
                for (int jj = 0; jj < 4; ++jj) wprev[jj] = wcur[jj];
            }
            float* op = out + (size_t)plane * (H_ * W_) + (h0 + y0) * W_ + x0;
            *(float2*)(op)      = make_float2(pairsum(acc00), pairsum(acc01));
            *(float2*)(op + W_) = make_float2(pairsum(acc10), pairsum(acc11));
        }

        // stage C: split staged regs into sm[buf^1] (paired STS.128)
        if (more) {
            if (tid < K_ * 8) {
                int j = tid & 7;
                float2 v2 = make_float2(0.0f, 0.0f);
                if (j < K_) {
                    float wv = w[(nplane % C_) * (K_ * K_) + (tid >> 3) * K_ + j];
                    v2 = make_float2(wv, usplit(wv).x);
                }
                sw[buf ^ 1][tid] = v2;
            }
#pragma unroll
            for (int kk = 0; kk < 3; ++kk) {
                int pid = tid + kk * NTHR;
                if (pid < HCELLS) {
                    int idx = pid * 2;
                    if ((idx & 63) < 62) {
                        float2 a = usplit(va[kk]), b = usplit(vb[kk]);
                        *(float4*)&sm[buf ^ 1][idx] =
                            make_float4(a.x, a.y, b.x, b.y);
                    }
                }
            }
        }
        __syncthreads();
    }
}

extern "C" void kernel_launch(void* const* d_in, const int* in_sizes, int n_in,
                              void* d_out, int out_size) {
    const float* x  = (const float*)d_in[0];   // (4,192,56,56) f32
    const float* wt = (const float*)d_in[1];   // (192,1,7,7)  f32
    float* out = (float*)d_out;                // (4,192,56,56) f32
    (void)in_sizes; (void)n_in; (void)out_size;
    waconv_kernel<<<NBLK, NTHR>>>(x, wt, out);
}